// round 10
// baseline (speedup 1.0000x reference)
#include <cuda_runtime.h>
#include <cuda_bf16.h>

#define BB 16
#define SS 4096
#define DD 1024

#define GSPLIT 32      // split-K for the weight GEMVs
#define ATT_SPLIT 64   // 64-row sequence tiles (grid 64 x 16)
#define FIN_GRID  256

// ---------------- scratch (device globals; no allocations) ----------------
__device__ float g_q_part[GSPLIT][BB * DD];
__device__ float g_q[BB * DD];
__device__ float g_qk[BB * DD];
__device__ float g_esum_part[BB][ATT_SPLIT];
__device__ float g_ctx_part[ATT_SPLIT][BB * DD];
__device__ float g_ctx[BB * DD];
__device__ float g_out_part[GSPLIT][BB * DD];
__device__ unsigned g_ctr[4];   // zero-initialized; restored to 0 on every exit

// ---------------------------------------------------------------------------
// Device-wide barrier for an N-block kernel where all blocks are resident.
// ---------------------------------------------------------------------------
template <int N>
__device__ __forceinline__ void grid_barrier(unsigned* c) {
    __syncthreads();
    if (threadIdx.x == 0) {
        __threadfence();
        atomicAdd(c, 1u);
        while (atomicAdd(c, 0u) < (unsigned)N) { }
        __threadfence();
    }
    __syncthreads();
}

template <int N>
__device__ __forceinline__ void barrier_reset_exit() {
    __syncthreads();
    if (threadIdx.x == 0) {
        __threadfence();
        unsigned old = atomicAdd(&g_ctr[3], 1u);
        if (old == (unsigned)(N - 1)) {
            atomicExch(&g_ctr[0], 0u);
            atomicExch(&g_ctr[1], 0u);
            atomicExch(&g_ctr[2], 0u);
            atomicExch(&g_ctr[3], 0u);
        }
    }
}

// ---------------------------------------------------------------------------
// K1: split-K batched GEMV partials (R5, validated).
// grid (DD/128 = 8, GSPLIT = 32) = 256 blocks, block 128.
// ---------------------------------------------------------------------------
__global__ void __launch_bounds__(128) gemv_part_kernel(const float* __restrict__ X,
                                                        const float* __restrict__ W,
                                                        float* __restrict__ part) {
    const int h  = blockIdx.x * 128 + threadIdx.x;
    const int IR = DD / GSPLIT;                     // 32
    const int i0 = blockIdx.y * IR;

    __shared__ float xs[BB][DD / GSPLIT];
    for (int t = threadIdx.x; t < BB * IR; t += 128) {
        int b = t >> 5, ii = t & 31;
        xs[b][ii] = X[b * DD + i0 + ii];
    }
    __syncthreads();

    float acc[BB];
#pragma unroll
    for (int b = 0; b < BB; b++) acc[b] = 0.f;

#pragma unroll 4
    for (int ii = 0; ii < IR; ii++) {
        float w = W[(size_t)(i0 + ii) * DD + h];
#pragma unroll
        for (int b = 0; b < BB; b++) acc[b] += xs[b][ii] * w;
    }

    float* p = part + (size_t)blockIdx.y * (BB * DD);
#pragma unroll
    for (int b = 0; b < BB; b++) p[b * DD + h] = acc[b];
}

// ---------------------------------------------------------------------------
// K2: sum GSPLIT partials (R5, validated). grid 128, block 128.
// ---------------------------------------------------------------------------
__global__ void __launch_bounds__(128) reduce32_kernel(const float* __restrict__ part,
                                                       float* __restrict__ out) {
    const int idx = blockIdx.x * 128 + threadIdx.x;
    float s = 0.f;
#pragma unroll
    for (int k = 0; k < GSPLIT; k++) s += part[(size_t)k * (BB * DD) + idx];
    out[idx] = s;
}

// ---------------------------------------------------------------------------
// K3: qk[b,i] = sum_h Wk[i,h] * q[b,h]  (R5, validated).
// grid 128, block 256 (8 warps); 64 KB smem staging of q.
// ---------------------------------------------------------------------------
__global__ void qk_kernel(const float* __restrict__ Wk) {
    const int warp = threadIdx.x >> 5;
    const int lane = threadIdx.x & 31;
    const int i = blockIdx.x * 8 + warp;

    __shared__ __align__(16) float qs[BB][DD];
    for (int t = threadIdx.x; t < BB * DD / 4; t += 256) {
        ((float4*)&qs[0][0])[t] = ((const float4*)g_q)[t];
    }
    __syncthreads();

    const float4* wrow = (const float4*)(Wk + (size_t)i * DD);

    float acc[BB];
#pragma unroll
    for (int b = 0; b < BB; b++) acc[b] = 0.f;

#pragma unroll
    for (int c = 0; c < DD / 4; c += 32) {
        float4 w4 = wrow[c + lane];
        int h = (c + lane) * 4;
#pragma unroll
        for (int b = 0; b < BB; b++) {
            acc[b] += w4.x * qs[b][h] + w4.y * qs[b][h + 1]
                    + w4.z * qs[b][h + 2] + w4.w * qs[b][h + 3];
        }
    }
#pragma unroll
    for (int b = 0; b < BB; b++) {
        float v = acc[b];
#pragma unroll
        for (int o = 16; o > 0; o >>= 1) v += __shfl_down_sync(0xffffffffu, v, o);
        if (lane == 0) g_qk[b * DD + i] = v;
    }
}

// ---------------------------------------------------------------------------
// K4: fused attention over a 64-row tile of one batch (R6, validated).
// grid (64, 16), block 256.
// ---------------------------------------------------------------------------
__global__ void __launch_bounds__(256) attn_fused_kernel(const float* __restrict__ key,
                                                         const float* __restrict__ value) {
    const int b  = blockIdx.y;
    const int s0 = blockIdx.x * 64;
    const int warp = threadIdx.x >> 5;
    const int lane = threadIdx.x & 31;

    __shared__ __align__(16) float qk_s[DD];
    __shared__ float w_s[64];
    __shared__ float red[8];

    ((float4*)qk_s)[threadIdx.x] = ((const float4*)(g_qk + b * DD))[threadIdx.x];
    __syncthreads();

    const float4* qrow = (const float4*)qk_s;
    const float4* kbase = (const float4*)(key + ((size_t)b * SS + s0) * DD);

    // Phase A: 8 rows per warp, processed as 4 pairs
    float esum = 0.f;
#pragma unroll
    for (int p = 0; p < 4; p++) {
        const int r0 = warp * 8 + p * 2;
        const int r1 = r0 + 1;
        const float4* k0 = kbase + (size_t)r0 * (DD / 4);
        const float4* k1 = kbase + (size_t)r1 * (DD / 4);

        float a0 = 0.f, a1 = 0.f;
#pragma unroll
        for (int c = 0; c < DD / 4; c += 32) {
            float4 ka = __ldcs(&k0[c + lane]);
            float4 kb = __ldcs(&k1[c + lane]);
            float4 q4 = qrow[c + lane];
            a0 += ka.x * q4.x + ka.y * q4.y + ka.z * q4.z + ka.w * q4.w;
            a1 += kb.x * q4.x + kb.y * q4.y + kb.z * q4.z + kb.w * q4.w;
        }
#pragma unroll
        for (int o = 16; o > 0; o >>= 1) {
            a0 += __shfl_down_sync(0xffffffffu, a0, o);
            a1 += __shfl_down_sync(0xffffffffu, a1, o);
        }
        if (lane == 0) {
            float e0 = expf(a0 * 0.03125f);   // 1/sqrt(1024); bounded, no max shift
            float e1 = expf(a1 * 0.03125f);
            w_s[r0] = e0;
            w_s[r1] = e1;
            esum += e0 + e1;
        }
    }
    if (lane == 0) red[warp] = esum;
    __syncthreads();

    if (threadIdx.x == 0) {
        float s = 0.f;
#pragma unroll
        for (int w = 0; w < 8; w++) s += red[w];
        g_esum_part[b][blockIdx.x] = s;
    }

    // Phase B: thread owns one float4 of the 1024 output dims
    const float4* vbase = (const float4*)(value + ((size_t)b * SS + s0) * DD);
    const int i4 = threadIdx.x;

    float4 acc = make_float4(0.f, 0.f, 0.f, 0.f);
#pragma unroll 16
    for (int ss = 0; ss < 64; ss++) {
        float w = w_s[ss];
        float4 v = __ldcs(&vbase[(size_t)ss * (DD / 4) + i4]);
        acc.x += w * v.x; acc.y += w * v.y; acc.z += w * v.z; acc.w += w * v.w;
    }
    ((float4*)g_ctx_part[blockIdx.x])[b * (DD / 4) + i4] = acc;
}

// ---------------------------------------------------------------------------
// K5: FINISH (R6-validated version WITH the phase-1 bounds check):
// (1) ctx = (sum tile partials)/(sum exp), (2) out partials = ctx @ Wv,
// (3) reduce -> d_out.  grid 256, block 128.
// ---------------------------------------------------------------------------
__global__ void __launch_bounds__(128) finish_kernel(const float* __restrict__ Wv,
                                                     float* __restrict__ out) {
    __shared__ float xs[BB][DD / GSPLIT];   // 2 KB
    const int tid = threadIdx.x;
    const int bid = blockIdx.x;

    // ---- Phase 1: normalize ctx (16384 elems; grid covers 32768 threads,
    //      the bounds check is load-bearing: without it we write past g_ctx
    //      and race with other blocks' g_ctx_part reads) ----
    {
        const int idx = bid * 128 + tid;
        if (idx < BB * DD) {
            const int b = idx >> 10;          // uniform within warp
            const int lane = tid & 31;
            float e = g_esum_part[b][lane] + g_esum_part[b][lane + 32];
#pragma unroll
            for (int o = 16; o > 0; o >>= 1) e += __shfl_down_sync(0xffffffffu, e, o);
            const float inv = 1.f / __shfl_sync(0xffffffffu, e, 0);

            float s = 0.f;
#pragma unroll
            for (int k = 0; k < ATT_SPLIT; k++) s += g_ctx_part[k][idx];
            g_ctx[idx] = s * inv;
        }
    }
    grid_barrier<FIN_GRID>(&g_ctr[0]);

    // ---- Phase 2: out partials. bid -> (hchunk = bid&7, split = bid>>3) ----
    {
        const int h  = (bid & 7) * 128 + tid;
        const int sp = bid >> 3;
        const int i0 = sp * (DD / GSPLIT);

        for (int t = tid; t < BB * 32; t += 128) {
            int b = t >> 5, ii = t & 31;
            (&xs[0][0])[t] = g_ctx[b * DD + i0 + ii];
        }
        __syncthreads();

        float acc[BB];
#pragma unroll
        for (int b = 0; b < BB; b++) acc[b] = 0.f;
#pragma unroll 4
        for (int ii = 0; ii < 32; ii++) {
            float w = Wv[(size_t)(i0 + ii) * DD + h];
#pragma unroll
            for (int b = 0; b < BB; b++) acc[b] += xs[b][ii] * w;
        }
#pragma unroll
        for (int b = 0; b < BB; b++) g_out_part[sp][b * DD + h] = acc[b];
    }
    grid_barrier<FIN_GRID>(&g_ctr[1]);

    // ---- Phase 3: reduce 32 partials -> d_out ----
    {
        const int idx = bid * 128 + tid;
        if (idx < BB * DD) {
            float s = 0.f;
#pragma unroll
            for (int k = 0; k < GSPLIT; k++) s += g_out_part[k][idx];
            out[idx] = s;
        }
    }
    barrier_reset_exit<FIN_GRID>();
}

// ---------------------------------------------------------------------------
extern "C" void kernel_launch(void* const* d_in, const int* in_sizes, int n_in,
                              void* d_out, int out_size) {
    const float* key   = (const float*)d_in[0];
    const float* query = (const float*)d_in[1];
    const float* value = (const float*)d_in[2];
    const float* Wk    = (const float*)d_in[3];
    const float* Wq    = (const float*)d_in[4];
    const float* Wv    = (const float*)d_in[5];
    float* out = (float*)d_out;

    float *d_q, *d_qpart;
    cudaGetSymbolAddress((void**)&d_q, g_q);
    cudaGetSymbolAddress((void**)&d_qpart, g_q_part);

    // q = query @ Wq
    gemv_part_kernel<<<dim3(DD / 128, GSPLIT), 128>>>(query, Wq, d_qpart);
    reduce32_kernel<<<BB * DD / 128, 128>>>(d_qpart, d_q);
    // qk[b] = Wk @ q[b]
    qk_kernel<<<DD / 8, 256>>>(Wk);
    // fused: scores -> exp -> weighted value partials (both big passes)
    attn_fused_kernel<<<dim3(ATT_SPLIT, BB), 256>>>(key, value);
    // ctx normalize ; out = ctx@Wv ; out reduce  (one kernel, 2 grid barriers)
    finish_kernel<<<FIN_GRID, 128>>>(Wv, out);
}